// round 12
// baseline (speedup 1.0000x reference)
#include <cuda_runtime.h>
#include <cuda_fp16.h>
#include <cstdint>
#include <cstddef>

// Problem constants (fixed by the dataset)
#define NV    20000            // vertices per batch
#define NVT   80000            // B * N
#define KN    16               // neighbors
#define MM    9                // kernels
#define CC    64               // in channels
#define OO    64               // out channels
#define GK    576              // GEMM K (M * C)

// Device-global scratch (sanctioned workaround for no-alloc rule)
__device__ float g_uxc[NVT * 12];                        // ux + c (pad 12)
__device__ float g_vxp[NVT * 12];                        // vx     (pad 12)
__device__ __align__(16) __half g_xh[(size_t)NVT * CC];  // x in fp16
__device__ __align__(16) __half g_s[(size_t)NVT * GK];   // s (fp16, scl folded)
__device__ __align__(16) __half g_wb[OO * GK];           // B[o][k] = W[m][o][c]

// ---- packed fp32x2 helpers ----
__device__ __forceinline__ void fma2(unsigned long long& acc,
                                     unsigned long long a,
                                     unsigned long long b) {
    asm("fma.rn.f32x2 %0, %1, %2, %0;" : "+l"(acc) : "l"(a), "l"(b));
}
__device__ __forceinline__ unsigned long long pack2(float x, float y) {
    unsigned long long r;
    asm("mov.b64 %0, {%1, %2};" : "=l"(r) : "f"(x), "f"(y));
    return r;
}
__device__ __forceinline__ float2 unpack2(unsigned long long a) {
    float2 r;
    asm("mov.b64 {%0, %1}, %2;" : "=f"(r.x), "=f"(r.y) : "l"(a));
    return r;
}
// ---- half2 bit-cast (header intrinsic __half2_as_uint doesn't exist) ----
__device__ __forceinline__ uint32_t h2u(__half2 h) {
    uint32_t r;
    memcpy(&r, &h, 4);
    return r;
}
// pack two floats straight to a half2 bit pattern
__device__ __forceinline__ uint32_t f2h2(float x, float y) {
    return h2u(__floats2half2_rn(x, y));
}
// ---- cp.async helpers ----
__device__ __forceinline__ void cpa16(uint32_t dst_smem, const void* src) {
    asm volatile("cp.async.cg.shared.global [%0], [%1], 16;"
                 :: "r"(dst_smem), "l"(src));
}
__device__ __forceinline__ void cpa_commit() {
    asm volatile("cp.async.commit_group;");
}
__device__ __forceinline__ void cpa_wait0() {
    asm volatile("cp.async.wait_group 0;");
}
__device__ __forceinline__ uint32_t smem_u32(const void* p) {
    uint32_t a;
    asm("{ .reg .u64 t; cvta.to.shared.u64 t, %1; cvt.u32.u64 %0, t; }"
        : "=r"(a) : "l"(p));
    return a;
}
// ---- tensor-core primitives (baseline PTX, sm_80+) ----
__device__ __forceinline__ void ldsm4(uint32_t& r0, uint32_t& r1, uint32_t& r2,
                                      uint32_t& r3, uint32_t addr) {
    asm volatile("ldmatrix.sync.aligned.m8n8.x4.shared.b16 {%0,%1,%2,%3}, [%4];"
                 : "=r"(r0), "=r"(r1), "=r"(r2), "=r"(r3) : "r"(addr));
}
__device__ __forceinline__ void mma16816(float* c, uint32_t a0, uint32_t a1,
                                         uint32_t a2, uint32_t a3,
                                         uint32_t b0, uint32_t b1) {
    asm volatile(
        "mma.sync.aligned.m16n8k16.row.col.f32.f16.f16.f32 "
        "{%0,%1,%2,%3}, {%4,%5,%6,%7}, {%8,%9}, {%0,%1,%2,%3};"
        : "+f"(c[0]), "+f"(c[1]), "+f"(c[2]), "+f"(c[3])
        : "r"(a0), "r"(a1), "r"(a2), "r"(a3), "r"(b0), "r"(b1));
}

// ---------------------------------------------------------------------------
// Kernel 1 (merged prep): blocks [0, 313) -> lane-per-vertex u/v projections
//                         (zero shuffles) + x -> fp16 copy
//                         blocks [313, +144) -> W -> fp16 B matrix [o][k]
// ---------------------------------------------------------------------------
#define UVX_BLOCKS 313          // ceil(80000 / 256)

__global__ void __launch_bounds__(256)
feast_prep(const float* __restrict__ x, const float* __restrict__ u,
           const float* __restrict__ v, const float* __restrict__ c,
           const float* __restrict__ W) {
    if (blockIdx.x < UVX_BLOCKS) {
        __shared__ float uv_sm[18 * 64];
        __shared__ float c_sm[MM];
        for (int i = threadIdx.x; i < 576; i += 256) {
            uv_sm[i]       = u[i];
            uv_sm[576 + i] = v[i];
        }
        if (threadIdx.x < MM) c_sm[threadIdx.x] = c[threadIdx.x];
        __syncthreads();

        const int gi = blockIdx.x * 256 + threadIdx.x;
        if (gi >= NVT) return;

        // load x row (64 fp32) into registers as fp32x2 packs
        unsigned long long xr[32];
        {
            const float4* xp = (const float4*)(x + (size_t)gi * CC);
            #pragma unroll
            for (int i = 0; i < 16; ++i) {
                const float4 t = xp[i];
                xr[2*i]   = pack2(t.x, t.y);
                xr[2*i+1] = pack2(t.z, t.w);
            }
        }
        // emit fp16 copy of the row (8 x STG.128)
        {
            uint4* dst = (uint4*)(g_xh + (size_t)gi * CC);
            #pragma unroll
            for (int i = 0; i < 8; ++i) {
                const float2 f0 = unpack2(xr[4*i]);
                const float2 f1 = unpack2(xr[4*i+1]);
                const float2 f2 = unpack2(xr[4*i+2]);
                const float2 f3 = unpack2(xr[4*i+3]);
                uint4 o;
                o.x = f2h2(f0.x, f0.y);
                o.y = f2h2(f1.x, f1.y);
                o.z = f2h2(f2.x, f2.y);
                o.w = f2h2(f3.x, f3.y);
                dst[i] = o;
            }
        }
        // 9 dual dot-products, fp32x2, u/v broadcast from smem
        #pragma unroll
        for (int m = 0; m < MM; ++m) {
            const unsigned long long* um = (const unsigned long long*)(uv_sm + m * 64);
            const unsigned long long* vm = (const unsigned long long*)(uv_sm + 576 + m * 64);
            unsigned long long pu = 0ull, pv = 0ull;
            #pragma unroll
            for (int i = 0; i < 32; ++i) {
                fma2(pu, xr[i], um[i]);
                fma2(pv, xr[i], vm[i]);
            }
            const float2 fu = unpack2(pu);
            const float2 fv = unpack2(pv);
            g_uxc[gi * 12 + m] = fu.x + fu.y + c_sm[m];
            g_vxp[gi * 12 + m] = fv.x + fv.y;
        }
    } else {
        const int tid = (blockIdx.x - UVX_BLOCKS) * 256 + threadIdx.x;
        if (tid >= MM * OO * CC) return;
        const int cc = tid & 63;
        const int o  = (tid >> 6) & 63;
        const int m  = tid >> 12;
        g_wb[o * GK + m * 64 + cc] = __float2half_rn(W[tid]);
    }
}

// ---------------------------------------------------------------------------
// Kernel 2: gather + softmax + s-accumulate -> g_s (fp16, scl folded)
// Stage A stores PRE-DUPLICATED q pairs; stage B gathers fp16 x (half traffic)
// ---------------------------------------------------------------------------
__global__ void __launch_bounds__(256)
feast_s(const int* __restrict__ adj) {
    __shared__ float q_sm[8 * 640];            // 20 floats per (vp, kk)

    const int tid  = threadIdx.x;
    const int w    = tid >> 5;
    const int lane = tid & 31;
    const int kk   = lane & 15;
    const int vp   = lane >> 4;
    const int bv0  = blockIdx.x * 32;
    float* qbuf = q_sm + w * 640;

    #pragma unroll
    for (int it = 0; it < 2; ++it) {
        const int vpair = w * 4 + it * 2;

        // ---- stage A: lane (vp, kk) -> softmax over M for one neighbor ----
        const int giA  = bv0 + vpair + vp;
        const int base = (giA / NV) * NV;
        const int a    = adj[giA * KN + kk];
        const unsigned bal = __ballot_sync(0xffffffffu, a > 0);
        const int deg0 = __popc(bal & 0xffffu);
        const int deg1 = __popc(bal >> 16);
        const float validf = (a > 0) ? 1.0f : 0.0f;
        const int j0 = (a > 0) ? (base + a - 1) : base;

        const float4 uc0 = *(const float4*)(g_uxc + giA * 12);
        const float4 uc1 = *(const float4*)(g_uxc + giA * 12 + 4);
        const float4 uc2 = *(const float4*)(g_uxc + giA * 12 + 8);
        const float4 vv0 = *(const float4*)(g_vxp + j0 * 12);
        const float4 vv1 = *(const float4*)(g_vxp + j0 * 12 + 4);
        const float4 vv2 = *(const float4*)(g_vxp + j0 * 12 + 8);
        float l[9];
        l[0] = (uc0.x + vv0.x) * validf; l[1] = (uc0.y + vv0.y) * validf;
        l[2] = (uc0.z + vv0.z) * validf; l[3] = (uc0.w + vv0.w) * validf;
        l[4] = (uc1.x + vv1.x) * validf; l[5] = (uc1.y + vv1.y) * validf;
        l[6] = (uc1.z + vv1.z) * validf; l[7] = (uc1.w + vv1.w) * validf;
        l[8] = (uc2.x + vv2.x) * validf;
        float mx = l[0];
        #pragma unroll
        for (int m = 1; m < 9; ++m) mx = fmaxf(mx, l[m]);
        float e[9], ssum = 0.f;
        #pragma unroll
        for (int m = 0; m < 9; ++m) { e[m] = __expf(l[m] - mx); ssum += e[m]; }
        float r;
        asm("rcp.approx.f32 %0, %1;" : "=f"(r) : "f"(ssum));
        r *= validf;

        float* qk = qbuf + (vp * 16 + kk) * 20;
        *(float4*)(qk)      = make_float4(e[0]*r, e[0]*r, e[1]*r, e[1]*r);
        *(float4*)(qk + 4)  = make_float4(e[2]*r, e[2]*r, e[3]*r, e[3]*r);
        *(float4*)(qk + 8)  = make_float4(e[4]*r, e[4]*r, e[5]*r, e[5]*r);
        *(float4*)(qk + 12) = make_float4(e[6]*r, e[6]*r, e[7]*r, e[7]*r);
        *(float4*)(qk + 16) = make_float4(e[8]*r, e[8]*r, __int_as_float(j0), 0.f);
        __syncwarp();

        // ---- stage B: lane <-> channel pair (2lane, 2lane+1); fp16 gathers ----
        #pragma unroll
        for (int vsel = 0; vsel < 2; ++vsel) {
            const float* qb = qbuf + vsel * 320;
            unsigned long long acc[9];
            #pragma unroll
            for (int m = 0; m < 9; ++m) acc[m] = 0ull;
            #pragma unroll 8
            for (int k2 = 0; k2 < KN; ++k2) {
                const ulonglong2 q01 = *(const ulonglong2*)(qb + k2 * 20);
                const ulonglong2 q23 = *(const ulonglong2*)(qb + k2 * 20 + 4);
                const ulonglong2 q45 = *(const ulonglong2*)(qb + k2 * 20 + 8);
                const ulonglong2 q67 = *(const ulonglong2*)(qb + k2 * 20 + 12);
                const ulonglong2 q8j = *(const ulonglong2*)(qb + k2 * 20 + 16);
                const int j2 = (int)(uint32_t)(q8j.y & 0xffffffffull);
                const __half2 h = ((const __half2*)(g_xh + (size_t)j2 * CC))[lane];
                const float2 xf = __half22float2(h);
                const unsigned long long xx = pack2(xf.x, xf.y);
                fma2(acc[0], q01.x, xx); fma2(acc[1], q01.y, xx);
                fma2(acc[2], q23.x, xx); fma2(acc[3], q23.y, xx);
                fma2(acc[4], q45.x, xx); fma2(acc[5], q45.y, xx);
                fma2(acc[6], q67.x, xx); fma2(acc[7], q67.y, xx);
                fma2(acc[8], q8j.x, xx);
            }
            const int dg = vsel ? deg1 : deg0;
            const float scl = (dg > 0) ? (1.0f / (float)dg) : 0.0f;
            uint32_t* srow = (uint32_t*)(g_s + (size_t)(bv0 + vpair + vsel) * GK);
            #pragma unroll
            for (int m = 0; m < 9; ++m) {
                const float2 f = unpack2(acc[m]);
                srow[m * 32 + lane] = f2h2(f.x * scl, f.y * scl);
            }
        }
        __syncwarp();
    }
}

// ---------------------------------------------------------------------------
// Kernel 3: fp16 HMMA GEMM  out[80000,64] = g_s[.,576] @ g_wb^T + bias
// 128-row x 64-col CTA tile, 8 warps (warp = 16 rows x 64 cols), K chunks of
// 64 halfs (128 B rows), cp.async double-buffered, SW128 swizzle, ldmatrix.x4.
// ---------------------------------------------------------------------------
#define ACHB 16384                       // A chunk: 128 rows x 128 B (64 halfs)
#define BCHB 8192                        // B chunk:  64 rows x 128 B
#define PERBUF (ACHB + BCHB)             // 24576
#define GSMEM (2 * PERBUF + 1024)        // + 1024 alignment slack

__global__ void __launch_bounds__(256, 2)
feast_gemm(const float* __restrict__ bias, float* __restrict__ out) {
    extern __shared__ char smem[];
    const uint32_t sraw = smem_u32(smem);
    const uint32_t sb   = (sraw + 1023u) & ~1023u;     // SW128 needs 1KB align
    const uint32_t abase[2] = { sb, sb + PERBUF };
    const uint32_t bbase[2] = { sb + ACHB, sb + PERBUF + ACHB };

    const int tid  = threadIdx.x;
    const int w    = tid >> 5;
    const int lane = tid & 31;
    const int row0 = blockIdx.x * 128;

    // ldmatrix lane addressing (shared by A and B tiles)
    const int grp = lane >> 3;                 // 0..3 -> matrix index
    const int rr  = lane & 7;                  // row within matrix
    const int mrow = (grp & 1) * 8 + rr;       // row offset within 16-row group
    const int mcol = (grp >> 1) * 16;          // byte col offset (0 or 16)

    // stage K-chunk ch (64 halfs) into buffer b
    auto stage = [&](int ch, int b) {
        const __half* asrc = g_s + (size_t)row0 * GK + ch * 64;
        #pragma unroll
        for (int i = 0; i < 4; ++i) {
            const int uu = tid + i * 256;          // 1024 16B units
            const int row = uu >> 3, cu = uu & 7;
            uint32_t off = (uint32_t)(row * 128 + cu * 16);
            off ^= (off >> 3) & 0x70;
            cpa16(abase[b] + off, asrc + (size_t)row * GK + cu * 8);
        }
        const __half* bsrc = g_wb + ch * 64;
        #pragma unroll
        for (int i = 0; i < 2; ++i) {
            const int uu = tid + i * 256;          // 512 16B units
            const int row = uu >> 3, cu = uu & 7;
            uint32_t off = (uint32_t)(row * 128 + cu * 16);
            off ^= (off >> 3) & 0x70;
            cpa16(bbase[b] + off, bsrc + (size_t)row * GK + cu * 8);
        }
        cpa_commit();
    };

    float acc[8][4];
    #pragma unroll
    for (int j = 0; j < 8; ++j)
        #pragma unroll
        for (int p = 0; p < 4; ++p) acc[j][p] = 0.f;

    stage(0, 0);

    for (int ch = 0; ch < 9; ++ch) {
        cpa_wait0();
        __syncthreads();                       // chunk ch resident; prev buf free

        if (ch < 8) stage(ch + 1, (ch + 1) & 1);

        const uint32_t ab = abase[ch & 1];
        const uint32_t bb = bbase[ch & 1];
        #pragma unroll
        for (int k16 = 0; k16 < 4; ++k16) {    // 16 halfs K per step = 32 bytes
            uint32_t aoff = (uint32_t)((w * 16 + mrow) * 128 + mcol + k16 * 32);
            aoff ^= (aoff >> 3) & 0x70;
            uint32_t a0, a1, a2, a3;
            ldsm4(a0, a1, a2, a3, ab + aoff);
            #pragma unroll
            for (int ng = 0; ng < 4; ++ng) {   // n in groups of 16
                uint32_t boff = (uint32_t)((ng * 16 + mrow) * 128 + mcol + k16 * 32);
                boff ^= (boff >> 3) & 0x70;
                uint32_t b0, b1, b2, b3;
                ldsm4(b0, b1, b2, b3, bb + boff);
                mma16816(acc[ng * 2],     a0, a1, a2, a3, b0, b2);
                mma16816(acc[ng * 2 + 1], a0, a1, a2, a3, b1, b3);
            }
        }
    }

    // ---- epilogue: C frags + bias -> gmem ----
    const int crow = row0 + w * 16 + (lane >> 2);
    const int ccol = (lane & 3) * 2;
    #pragma unroll
    for (int j = 0; j < 8; ++j) {
        const int nb = (j >> 1) * 16 + (j & 1) * 8 + ccol;
        const float2 bv = *(const float2*)(bias + nb);
        *(float2*)(out + (size_t)crow * OO + nb) =
            make_float2(acc[j][0] + bv.x, acc[j][1] + bv.y);
        *(float2*)(out + (size_t)(crow + 8) * OO + nb) =
            make_float2(acc[j][2] + bv.x, acc[j][3] + bv.y);
    }
}

// ---------------------------------------------------------------------------
// Host launcher (graph-capturable: kernel launches only)
// ---------------------------------------------------------------------------
extern "C" void kernel_launch(void* const* d_in, const int* in_sizes, int n_in,
                              void* d_out, int out_size) {
    const float* x   = (const float*)d_in[0];  // [B,N,C]
    const int*   adj = (const int*)  d_in[1];  // [B,N,K]
    const float* W   = (const float*)d_in[2];  // [M,O,C]
    const float* b   = (const float*)d_in[3];  // [O]
    const float* u   = (const float*)d_in[4];  // [M,C]
    const float* v   = (const float*)d_in[5];  // [M,C]
    const float* c   = (const float*)d_in[6];  // [M]
    float* out = (float*)d_out;

    feast_prep<<<UVX_BLOCKS + (MM * OO * CC + 255) / 256, 256>>>(x, u, v, c, W);
    feast_s<<<NVT / 32, 256>>>(adj);

    cudaFuncSetAttribute(feast_gemm, cudaFuncAttributeMaxDynamicSharedMemorySize,
                         GSMEM);
    feast_gemm<<<NVT / 128, 256, GSMEM>>>(b, out);
}

// round 13
// speedup vs baseline: 1.0851x; 1.0851x over previous
#include <cuda_runtime.h>
#include <cuda_fp16.h>
#include <cstdint>
#include <cstddef>
#include <cstring>

// Problem constants (fixed by the dataset)
#define NV    20000            // vertices per batch
#define NVT   80000            // B * N
#define KN    16               // neighbors
#define MM    9                // kernels
#define CC    64               // in channels
#define OO    64               // out channels
#define GK    576              // GEMM K (M * C)

// Device-global scratch (sanctioned workaround for no-alloc rule)
__device__ float g_uxc[NVT * 12];                        // ux + c (pad 12)
__device__ float g_vxp[NVT * 12];                        // vx     (pad 12)
__device__ __align__(16) __half g_xh[(size_t)NVT * CC];  // x in fp16
__device__ __align__(16) __half g_s[(size_t)NVT * GK];   // s (fp16, scl folded)
__device__ __align__(16) __half g_wb[OO * GK];           // B[o][k] = W[m][o][c]

// ---- packed fp32x2 helpers ----
__device__ __forceinline__ void fma2(unsigned long long& acc,
                                     unsigned long long a,
                                     unsigned long long b) {
    asm("fma.rn.f32x2 %0, %1, %2, %0;" : "+l"(acc) : "l"(a), "l"(b));
}
__device__ __forceinline__ unsigned long long pack2(float x, float y) {
    unsigned long long r;
    asm("mov.b64 %0, {%1, %2};" : "=l"(r) : "f"(x), "f"(y));
    return r;
}
__device__ __forceinline__ float2 unpack2(unsigned long long a) {
    float2 r;
    asm("mov.b64 {%0, %1}, %2;" : "=f"(r.x), "=f"(r.y) : "l"(a));
    return r;
}
// ---- half2 bit-cast helpers ----
__device__ __forceinline__ uint32_t h2u(__half2 h) {
    uint32_t r;
    memcpy(&r, &h, 4);
    return r;
}
__device__ __forceinline__ uint32_t f2h2(float x, float y) {
    return h2u(__floats2half2_rn(x, y));
}
// ---- cp.async helpers ----
__device__ __forceinline__ void cpa16(uint32_t dst_smem, const void* src) {
    asm volatile("cp.async.cg.shared.global [%0], [%1], 16;"
                 :: "r"(dst_smem), "l"(src));
}
__device__ __forceinline__ void cpa_commit() {
    asm volatile("cp.async.commit_group;");
}
__device__ __forceinline__ void cpa_wait0() {
    asm volatile("cp.async.wait_group 0;");
}
__device__ __forceinline__ uint32_t smem_u32(const void* p) {
    uint32_t a;
    asm("{ .reg .u64 t; cvta.to.shared.u64 t, %1; cvt.u32.u64 %0, t; }"
        : "=r"(a) : "l"(p));
    return a;
}
// ---- tensor-core primitives (baseline PTX, sm_75+/80+) ----
__device__ __forceinline__ void ldsm4(uint32_t& r0, uint32_t& r1, uint32_t& r2,
                                      uint32_t& r3, uint32_t addr) {
    asm volatile("ldmatrix.sync.aligned.m8n8.x4.shared.b16 {%0,%1,%2,%3}, [%4];"
                 : "=r"(r0), "=r"(r1), "=r"(r2), "=r"(r3) : "r"(addr));
}
__device__ __forceinline__ void ldsm4t(uint32_t& r0, uint32_t& r1, uint32_t& r2,
                                       uint32_t& r3, uint32_t addr) {
    asm volatile("ldmatrix.sync.aligned.m8n8.x4.trans.shared.b16 {%0,%1,%2,%3}, [%4];"
                 : "=r"(r0), "=r"(r1), "=r"(r2), "=r"(r3) : "r"(addr));
}
__device__ __forceinline__ void mma16816(float* c, uint32_t a0, uint32_t a1,
                                         uint32_t a2, uint32_t a3,
                                         uint32_t b0, uint32_t b1) {
    asm volatile(
        "mma.sync.aligned.m16n8k16.row.col.f32.f16.f16.f32 "
        "{%0,%1,%2,%3}, {%4,%5,%6,%7}, {%8,%9}, {%0,%1,%2,%3};"
        : "+f"(c[0]), "+f"(c[1]), "+f"(c[2]), "+f"(c[3])
        : "r"(a0), "r"(a1), "r"(a2), "r"(a3), "r"(b0), "r"(b1));
}

// ---------------------------------------------------------------------------
// Kernel 1 (merged prep): blocks [0, 625) -> lane-PAIR-per-vertex projections
//                         + x -> fp16 copy; blocks [625, +144) -> W -> fp16 B
// ---------------------------------------------------------------------------
#define UVX_BLOCKS 625          // 80000 / 128 vertices per block

__global__ void __launch_bounds__(256)
feast_prep(const float* __restrict__ x, const float* __restrict__ u,
           const float* __restrict__ v, const float* __restrict__ c,
           const float* __restrict__ W) {
    if (blockIdx.x < UVX_BLOCKS) {
        __shared__ float uv_sm[18 * 64];
        __shared__ float c_sm[MM];
        for (int i = threadIdx.x; i < 576; i += 256) {
            uv_sm[i]       = u[i];
            uv_sm[576 + i] = v[i];
        }
        if (threadIdx.x < MM) c_sm[threadIdx.x] = c[threadIdx.x];
        __syncthreads();

        const int pairid = threadIdx.x >> 1;       // vertex within block
        const int hf     = threadIdx.x & 1;        // channel half (0: 0-31)
        const int gi     = blockIdx.x * 128 + pairid;

        // load 32 channels into fp32x2 packs
        unsigned long long xr[16];
        {
            const float4* xp = (const float4*)(x + (size_t)gi * CC + hf * 32);
            #pragma unroll
            for (int i = 0; i < 8; ++i) {
                const float4 t = xp[i];
                xr[2*i]   = pack2(t.x, t.y);
                xr[2*i+1] = pack2(t.z, t.w);
            }
        }
        // fp16 copy of this half-row (4 x STG.128)
        {
            uint4* dst = (uint4*)(g_xh + (size_t)gi * CC + hf * 32);
            #pragma unroll
            for (int i = 0; i < 4; ++i) {
                const float2 f0 = unpack2(xr[4*i]);
                const float2 f1 = unpack2(xr[4*i+1]);
                const float2 f2 = unpack2(xr[4*i+2]);
                const float2 f3 = unpack2(xr[4*i+3]);
                uint4 o;
                o.x = f2h2(f0.x, f0.y);
                o.y = f2h2(f1.x, f1.y);
                o.z = f2h2(f2.x, f2.y);
                o.w = f2h2(f3.x, f3.y);
                dst[i] = o;
            }
        }
        // 9 dual half-dot-products + pair reduce
        #pragma unroll
        for (int m = 0; m < MM; ++m) {
            const unsigned long long* um =
                (const unsigned long long*)(uv_sm + m * 64 + hf * 32);
            const unsigned long long* vm =
                (const unsigned long long*)(uv_sm + 576 + m * 64 + hf * 32);
            unsigned long long pu = 0ull, pv = 0ull;
            #pragma unroll
            for (int i = 0; i < 16; ++i) {
                fma2(pu, xr[i], um[i]);
                fma2(pv, xr[i], vm[i]);
            }
            const float2 fu = unpack2(pu);
            const float2 fv = unpack2(pv);
            float su = fu.x + fu.y;
            float sv = fv.x + fv.y;
            su += __shfl_xor_sync(0xffffffffu, su, 1);
            sv += __shfl_xor_sync(0xffffffffu, sv, 1);
            if (hf == 0) {
                g_uxc[gi * 12 + m] = su + c_sm[m];
                g_vxp[gi * 12 + m] = sv;
            }
        }
    } else {
        const int tid = (blockIdx.x - UVX_BLOCKS) * 256 + threadIdx.x;
        if (tid >= MM * OO * CC) return;
        const int cc = tid & 63;
        const int o  = (tid >> 6) & 63;
        const int m  = tid >> 12;
        g_wb[o * GK + m * 64 + cc] = __float2half_rn(W[tid]);
    }
}

// ---------------------------------------------------------------------------
// Kernel 2: gather + softmax + HMMA s-accumulate -> g_s
// Warp per vertex: s[9,64] = q[16,9(pad16)]^T @ x_gather[16,64] via 8 MMAs.
// ---------------------------------------------------------------------------
__global__ void __launch_bounds__(256)
feast_s(const int* __restrict__ adj) {
    __shared__ __align__(128) __half q_sm[8 * 16 * 24];   // 48B rows per warp
    __shared__ __align__(128) __half xs_sm[8 * 16 * 64];  // 128B rows, swizzled

    const int w    = threadIdx.x >> 5;
    const int lane = threadIdx.x & 31;
    const uint32_t qbase = smem_u32(q_sm)  + w * (16 * 48);
    const uint32_t xbase = smem_u32(xs_sm) + w * (16 * 128);

    // ldmatrix lane addressing (computed once)
    // A (trans on q[k][m] storage): mats m0k0, m8k0, m0k8, m8k8
    const int arow  = (lane & 7) + ((lane & 16) >> 1);       // k row
    const uint32_t aaddr = qbase + arow * 48 + ((lane & 8) << 1);
    // B (trans on x[k][n] storage): rows 0-15 twice, chunk pairs
    const int brow  = lane & 15;
    const int bsel  = lane >> 4;                             // 0 or 1

    for (int it = 0; it < 4; ++it) {
        const int gi   = blockIdx.x * 32 + it * 8 + w;
        const int base = (gi / NV) * NV;

        // ---- stage A: lanes 0-15 -> softmax over M for neighbor k = lane ----
        int a = 0;
        if (lane < 16) a = adj[gi * KN + lane];
        const unsigned bal = __ballot_sync(0xffffffffu, a > 0);
        const int deg = __popc(bal & 0xffffu);
        const int j0  = (a > 0) ? (base + a - 1) : base;

        if (lane < 16) {
            const float validf = (a > 0) ? 1.0f : 0.0f;
            const float4 uc0 = *(const float4*)(g_uxc + gi * 12);
            const float4 uc1 = *(const float4*)(g_uxc + gi * 12 + 4);
            const float4 uc2 = *(const float4*)(g_uxc + gi * 12 + 8);
            const float4 vv0 = *(const float4*)(g_vxp + j0 * 12);
            const float4 vv1 = *(const float4*)(g_vxp + j0 * 12 + 4);
            const float4 vv2 = *(const float4*)(g_vxp + j0 * 12 + 8);
            float l[9];
            l[0] = (uc0.x + vv0.x) * validf; l[1] = (uc0.y + vv0.y) * validf;
            l[2] = (uc0.z + vv0.z) * validf; l[3] = (uc0.w + vv0.w) * validf;
            l[4] = (uc1.x + vv1.x) * validf; l[5] = (uc1.y + vv1.y) * validf;
            l[6] = (uc1.z + vv1.z) * validf; l[7] = (uc1.w + vv1.w) * validf;
            l[8] = (uc2.x + vv2.x) * validf;
            float mx = l[0];
            #pragma unroll
            for (int m = 1; m < 9; ++m) mx = fmaxf(mx, l[m]);
            float e[9], ssum = 0.f;
            #pragma unroll
            for (int m = 0; m < 9; ++m) { e[m] = __expf(l[m] - mx); ssum += e[m]; }
            float r;
            asm("rcp.approx.f32 %0, %1;" : "=f"(r) : "f"(ssum));
            r *= validf;

            uint32_t* qr = (uint32_t*)(q_sm + (w * 16 + lane) * 24);
            qr[0] = f2h2(e[0]*r, e[1]*r);
            qr[1] = f2h2(e[2]*r, e[3]*r);
            qr[2] = f2h2(e[4]*r, e[5]*r);
            qr[3] = f2h2(e[6]*r, e[7]*r);
            qr[4] = f2h2(e[8]*r, 0.f);
            qr[5] = 0u; qr[6] = 0u; qr[7] = 0u;
        }
        __syncwarp();

        // ---- gather 16 neighbor fp16 rows into swizzled smem ----
        #pragma unroll
        for (int p = 0; p < 4; ++p) {
            const int idx = lane + p * 32;               // 0..127
            const int row = idx >> 3;                    // 0..15
            const int c16 = idx & 7;                     // 16B chunk
            const int jr  = __shfl_sync(0xffffffffu, j0, row);
            const uint4 val = *(const uint4*)(g_xh + (size_t)jr * CC + c16 * 8);
            const uint32_t off = row * 128 + (((c16 ^ row) & 7) << 4);
            *(uint4*)((char*)xs_sm + w * (16 * 128) + off) = val;
        }
        __syncwarp();

        // ---- A frag from q, then 8 MMAs over 4 B-ldmatrix ----
        uint32_t a0, a1, a2, a3;
        ldsm4t(a0, a1, a2, a3, aaddr);

        float acc[8][4];
        #pragma unroll
        for (int nb = 0; nb < 8; ++nb)
            #pragma unroll
            for (int p = 0; p < 4; ++p) acc[nb][p] = 0.f;

        #pragma unroll
        for (int q = 0; q < 4; ++q) {
            const int chunk = 2 * q + bsel;
            const uint32_t baddr =
                xbase + brow * 128 + (((chunk ^ brow) & 7) << 4);
            uint32_t b0, b1, b2, b3;
            ldsm4t(b0, b1, b2, b3, baddr);
            mma16816(acc[2*q],     a0, a1, a2, a3, b0, b1);
            mma16816(acc[2*q + 1], a0, a1, a2, a3, b2, b3);
        }

        // ---- epilogue: scale by 1/deg, store fp16 s rows 0..8 ----
        const float scl = (deg > 0) ? (1.0f / (float)deg) : 0.0f;
        uint32_t* srow = (uint32_t*)(g_s + (size_t)gi * GK);
        const int m1 = lane >> 2;
        const int cw = lane & 3;
        #pragma unroll
        for (int nb = 0; nb < 8; ++nb) {
            const int col = nb * 8 + cw * 2;
            srow[(m1 * 64 + col) >> 1] = f2h2(acc[nb][0] * scl, acc[nb][1] * scl);
            if (m1 == 0)
                srow[(8 * 64 + col) >> 1] = f2h2(acc[nb][2] * scl, acc[nb][3] * scl);
        }
        __syncwarp();
    }
}

// ---------------------------------------------------------------------------
// Kernel 3: fp16 HMMA GEMM  out[80000,64] = g_s[.,576] @ g_wb^T + bias
// (unchanged from the validated round-12 kernel)
// ---------------------------------------------------------------------------
#define ACHB 16384                       // A chunk: 128 rows x 128 B (64 halfs)
#define BCHB 8192                        // B chunk:  64 rows x 128 B
#define PERBUF (ACHB + BCHB)             // 24576
#define GSMEM (2 * PERBUF + 1024)        // + 1024 alignment slack

__global__ void __launch_bounds__(256, 2)
feast_gemm(const float* __restrict__ bias, float* __restrict__ out) {
    extern __shared__ char smem[];
    const uint32_t sraw = smem_u32(smem);
    const uint32_t sb   = (sraw + 1023u) & ~1023u;
    const uint32_t abase[2] = { sb, sb + PERBUF };
    const uint32_t bbase[2] = { sb + ACHB, sb + PERBUF + ACHB };

    const int tid  = threadIdx.x;
    const int w    = tid >> 5;
    const int lane = tid & 31;
    const int row0 = blockIdx.x * 128;

    const int grp = lane >> 3;
    const int rr  = lane & 7;
    const int mrow = (grp & 1) * 8 + rr;
    const int mcol = (grp >> 1) * 16;

    auto stage = [&](int ch, int b) {
        const __half* asrc = g_s + (size_t)row0 * GK + ch * 64;
        #pragma unroll
        for (int i = 0; i < 4; ++i) {
            const int uu = tid + i * 256;
            const int row = uu >> 3, cu = uu & 7;
            uint32_t off = (uint32_t)(row * 128 + cu * 16);
            off ^= (off >> 3) & 0x70;
            cpa16(abase[b] + off, asrc + (size_t)row * GK + cu * 8);
        }
        const __half* bsrc = g_wb + ch * 64;
        #pragma unroll
        for (int i = 0; i < 2; ++i) {
            const int uu = tid + i * 256;
            const int row = uu >> 3, cu = uu & 7;
            uint32_t off = (uint32_t)(row * 128 + cu * 16);
            off ^= (off >> 3) & 0x70;
            cpa16(bbase[b] + off, bsrc + (size_t)row * GK + cu * 8);
        }
        cpa_commit();
    };

    float acc[8][4];
    #pragma unroll
    for (int j = 0; j < 8; ++j)
        #pragma unroll
        for (int p = 0; p < 4; ++p) acc[j][p] = 0.f;

    stage(0, 0);

    for (int ch = 0; ch < 9; ++ch) {
        cpa_wait0();
        __syncthreads();

        if (ch < 8) stage(ch + 1, (ch + 1) & 1);

        const uint32_t ab = abase[ch & 1];
        const uint32_t bb = bbase[ch & 1];
        #pragma unroll
        for (int k16 = 0; k16 < 4; ++k16) {
            uint32_t aoff = (uint32_t)((w * 16 + mrow) * 128 + mcol + k16 * 32);
            aoff ^= (aoff >> 3) & 0x70;
            uint32_t a0, a1, a2, a3;
            ldsm4(a0, a1, a2, a3, ab + aoff);
            #pragma unroll
            for (int ng = 0; ng < 4; ++ng) {
                uint32_t boff = (uint32_t)((ng * 16 + mrow) * 128 + mcol + k16 * 32);
                boff ^= (boff >> 3) & 0x70;
                uint32_t b0, b1, b2, b3;
                ldsm4(b0, b1, b2, b3, bb + boff);
                mma16816(acc[ng * 2],     a0, a1, a2, a3, b0, b2);
                mma16816(acc[ng * 2 + 1], a0, a1, a2, a3, b1, b3);
            }
        }
    }

    const int crow = row0 + w * 16 + (lane >> 2);
    const int ccol = (lane & 3) * 2;
    #pragma unroll
    for (int j = 0; j < 8; ++j) {
        const int nb = (j >> 1) * 16 + (j & 1) * 8 + ccol;
        const float2 bv = *(const float2*)(bias + nb);
        *(float2*)(out + (size_t)crow * OO + nb) =
            make_float2(acc[j][0] + bv.x, acc[j][1] + bv.y);
        *(float2*)(out + (size_t)(crow + 8) * OO + nb) =
            make_float2(acc[j][2] + bv.x, acc[j][3] + bv.y);
    }
}

// ---------------------------------------------------------------------------
// Host launcher (graph-capturable: kernel launches only)
// ---------------------------------------------------------------------------
extern "C" void kernel_launch(void* const* d_in, const int* in_sizes, int n_in,
                              void* d_out, int out_size) {
    const float* x   = (const float*)d_in[0];  // [B,N,C]
    const int*   adj = (const int*)  d_in[1];  // [B,N,K]
    const float* W   = (const float*)d_in[2];  // [M,O,C]
    const float* b   = (const float*)d_in[3];  // [O]
    const float* u   = (const float*)d_in[4];  // [M,C]
    const float* v   = (const float*)d_in[5];  // [M,C]
    const float* c   = (const float*)d_in[6];  // [M]
    float* out = (float*)d_out;

    feast_prep<<<UVX_BLOCKS + (MM * OO * CC + 255) / 256, 256>>>(x, u, v, c, W);
    feast_s<<<NVT / 32, 256>>>(adj);

    cudaFuncSetAttribute(feast_gemm, cudaFuncAttributeMaxDynamicSharedMemorySize,
                         GSMEM);
    feast_gemm<<<NVT / 128, 256, GSMEM>>>(b, out);
}

// round 14
// speedup vs baseline: 1.2680x; 1.1685x over previous
#include <cuda_runtime.h>
#include <cuda_fp16.h>
#include <cstdint>
#include <cstddef>
#include <cstring>

// Problem constants (fixed by the dataset)
#define NV    20000            // vertices per batch
#define NVT   80000            // B * N
#define KN    16               // neighbors
#define MM    9                // kernels
#define CC    64               // in channels
#define OO    64               // out channels
#define GK    576              // GEMM K (M * C)

// Device-global scratch (sanctioned workaround for no-alloc rule)
__device__ float g_uxc[NVT * 12];                        // ux + c (pad 12)
__device__ float g_vxp[NVT * 12];                        // vx     (pad 12)
__device__ __align__(16) __half g_xh[(size_t)NVT * CC];  // x in fp16
__device__ __align__(16) __half g_wb[OO * GK];           // B[o][k] = W[m][o][c]

// ---- packed fp32x2 helpers ----
__device__ __forceinline__ void fma2(unsigned long long& acc,
                                     unsigned long long a,
                                     unsigned long long b) {
    asm("fma.rn.f32x2 %0, %1, %2, %0;" : "+l"(acc) : "l"(a), "l"(b));
}
__device__ __forceinline__ unsigned long long pack2(float x, float y) {
    unsigned long long r;
    asm("mov.b64 %0, {%1, %2};" : "=l"(r) : "f"(x), "f"(y));
    return r;
}
__device__ __forceinline__ float2 unpack2(unsigned long long a) {
    float2 r;
    asm("mov.b64 {%0, %1}, %2;" : "=f"(r.x), "=f"(r.y) : "l"(a));
    return r;
}
// ---- half2 bit-cast helpers ----
__device__ __forceinline__ uint32_t h2u(__half2 h) {
    uint32_t r;
    memcpy(&r, &h, 4);
    return r;
}
__device__ __forceinline__ uint32_t f2h2(float x, float y) {
    return h2u(__floats2half2_rn(x, y));
}
// ---- cp.async helpers ----
__device__ __forceinline__ void cpa16(uint32_t dst_smem, const void* src) {
    asm volatile("cp.async.cg.shared.global [%0], [%1], 16;"
                 :: "r"(dst_smem), "l"(src));
}
__device__ __forceinline__ void cpa_commit() {
    asm volatile("cp.async.commit_group;");
}
__device__ __forceinline__ void cpa_wait0() {
    asm volatile("cp.async.wait_group 0;");
}
__device__ __forceinline__ uint32_t smem_u32(const void* p) {
    uint32_t a;
    asm("{ .reg .u64 t; cvta.to.shared.u64 t, %1; cvt.u32.u64 %0, t; }"
        : "=r"(a) : "l"(p));
    return a;
}
// ---- tensor-core primitives (baseline PTX, sm_75+/80+) ----
__device__ __forceinline__ void ldsm4(uint32_t& r0, uint32_t& r1, uint32_t& r2,
                                      uint32_t& r3, uint32_t addr) {
    asm volatile("ldmatrix.sync.aligned.m8n8.x4.shared.b16 {%0,%1,%2,%3}, [%4];"
                 : "=r"(r0), "=r"(r1), "=r"(r2), "=r"(r3) : "r"(addr));
}
__device__ __forceinline__ void ldsm4t(uint32_t& r0, uint32_t& r1, uint32_t& r2,
                                       uint32_t& r3, uint32_t addr) {
    asm volatile("ldmatrix.sync.aligned.m8n8.x4.trans.shared.b16 {%0,%1,%2,%3}, [%4];"
                 : "=r"(r0), "=r"(r1), "=r"(r2), "=r"(r3) : "r"(addr));
}
__device__ __forceinline__ void mma16816(float* c, uint32_t a0, uint32_t a1,
                                         uint32_t a2, uint32_t a3,
                                         uint32_t b0, uint32_t b1) {
    asm volatile(
        "mma.sync.aligned.m16n8k16.row.col.f32.f16.f16.f32 "
        "{%0,%1,%2,%3}, {%4,%5,%6,%7}, {%8,%9}, {%0,%1,%2,%3};"
        : "+f"(c[0]), "+f"(c[1]), "+f"(c[2]), "+f"(c[3])
        : "r"(a0), "r"(a1), "r"(a2), "r"(a3), "r"(b0), "r"(b1));
}
// per-group chunk rotation (16B granularity): spreads same-row chunks across banks
__device__ __forceinline__ int swzc(int c) {
    return (c & ~7) | ((c + (c >> 3)) & 7);
}

// ---------------------------------------------------------------------------
// Kernel 1 (merged prep): blocks [0, 625) -> lane-PAIR-per-vertex projections
//                         + x -> fp16 copy; blocks [625, +144) -> W -> fp16 B
// ---------------------------------------------------------------------------
#define UVX_BLOCKS 625          // 80000 / 128 vertices per block

__global__ void __launch_bounds__(256)
feast_prep(const float* __restrict__ x, const float* __restrict__ u,
           const float* __restrict__ v, const float* __restrict__ c,
           const float* __restrict__ W) {
    if (blockIdx.x < UVX_BLOCKS) {
        __shared__ float uv_sm[18 * 64];
        __shared__ float c_sm[MM];
        for (int i = threadIdx.x; i < 576; i += 256) {
            uv_sm[i]       = u[i];
            uv_sm[576 + i] = v[i];
        }
        if (threadIdx.x < MM) c_sm[threadIdx.x] = c[threadIdx.x];
        __syncthreads();

        const int pairid = threadIdx.x >> 1;       // vertex within block
        const int hf     = threadIdx.x & 1;        // channel half (0: 0-31)
        const int gi     = blockIdx.x * 128 + pairid;

        unsigned long long xr[16];
        {
            const float4* xp = (const float4*)(x + (size_t)gi * CC + hf * 32);
            #pragma unroll
            for (int i = 0; i < 8; ++i) {
                const float4 t = xp[i];
                xr[2*i]   = pack2(t.x, t.y);
                xr[2*i+1] = pack2(t.z, t.w);
            }
        }
        {
            uint4* dst = (uint4*)(g_xh + (size_t)gi * CC + hf * 32);
            #pragma unroll
            for (int i = 0; i < 4; ++i) {
                const float2 f0 = unpack2(xr[4*i]);
                const float2 f1 = unpack2(xr[4*i+1]);
                const float2 f2 = unpack2(xr[4*i+2]);
                const float2 f3 = unpack2(xr[4*i+3]);
                uint4 o;
                o.x = f2h2(f0.x, f0.y);
                o.y = f2h2(f1.x, f1.y);
                o.z = f2h2(f2.x, f2.y);
                o.w = f2h2(f3.x, f3.y);
                dst[i] = o;
            }
        }
        #pragma unroll
        for (int m = 0; m < MM; ++m) {
            const unsigned long long* um =
                (const unsigned long long*)(uv_sm + m * 64 + hf * 32);
            const unsigned long long* vm =
                (const unsigned long long*)(uv_sm + 576 + m * 64 + hf * 32);
            unsigned long long pu = 0ull, pv = 0ull;
            #pragma unroll
            for (int i = 0; i < 16; ++i) {
                fma2(pu, xr[i], um[i]);
                fma2(pv, xr[i], vm[i]);
            }
            const float2 fu = unpack2(pu);
            const float2 fv = unpack2(pv);
            float su = fu.x + fu.y;
            float sv = fv.x + fv.y;
            su += __shfl_xor_sync(0xffffffffu, su, 1);
            sv += __shfl_xor_sync(0xffffffffu, sv, 1);
            if (hf == 0) {
                g_uxc[gi * 12 + m] = su + c_sm[m];
                g_vxp[gi * 12 + m] = sv;
            }
        }
    } else {
        const int tid = (blockIdx.x - UVX_BLOCKS) * 256 + threadIdx.x;
        if (tid >= MM * OO * CC) return;
        const int cc = tid & 63;
        const int o  = (tid >> 6) & 63;
        const int m  = tid >> 12;
        g_wb[o * GK + m * 64 + cc] = __float2half_rn(W[tid]);
    }
}

// ---------------------------------------------------------------------------
// Kernel 2 (FUSED): gather + softmax + HMMA s (to smem) + HMMA GEMM + bias
// CTA = 32 vertices. Phase 1: warp-per-vertex s[9,64] via 8 MMAs -> smem tile.
// Phase 2: out[32,64] = s_tile[32,576] @ Wb^T via HMMA, Wb cp.async staged.
// ---------------------------------------------------------------------------
// smem layout (bytes from base):
#define S_OFF   0                        // 32 rows x 1168 B (584 halfs)
#define S_ROWB  1168
#define XS_OFF  37376                    // 8 warps x 16 x 128 B
#define Q_OFF   53760                    // 8 warps x 16 x 48 B
#define B0_OFF  59904                    // Wb chunk buf 0 (8 KB)
#define B1_OFF  68096                    // Wb chunk buf 1 (8 KB)
#define FSMEM   76288

__global__ void __launch_bounds__(256, 2)
feast_fused(const int* __restrict__ adj, const float* __restrict__ bias,
            float* __restrict__ out) {
    extern __shared__ char smem[];
    const uint32_t sb    = smem_u32(smem);
    const uint32_t sbase = sb + S_OFF;
    const uint32_t qbase0 = sb + Q_OFF;
    const uint32_t xbase0 = sb + XS_OFF;
    const uint32_t bbase[2] = { sb + B0_OFF, sb + B1_OFF };

    const int tid  = threadIdx.x;
    const int w    = tid >> 5;
    const int lane = tid & 31;
    const int bv0  = blockIdx.x * 32;

    // stage Wb chunk ch (64 o-rows x 64 halfs, SW128 swizzled) into buffer b
    auto stageB = [&](int ch, int b) {
        const __half* bsrc = g_wb + ch * 64;
        #pragma unroll
        for (int i = 0; i < 2; ++i) {
            const int uu = tid + i * 256;
            const int row = uu >> 3, cu = uu & 7;
            uint32_t off = (uint32_t)(row * 128 + cu * 16);
            off ^= (off >> 3) & 0x70;
            cpa16(bbase[b] + off, bsrc + (size_t)row * GK + cu * 8);
        }
        cpa_commit();
    };
    stageB(0, 0);   // flows in under phase 1

    // ======================= PHASE 1 =======================
    const uint32_t qbase = qbase0 + w * (16 * 48);
    const uint32_t xbase = xbase0 + w * (16 * 128);
    const int arow = (lane & 7) + ((lane & 16) >> 1);
    const uint32_t aaddr1 = qbase + arow * 48 + ((lane & 8) << 1);
    const int brow = lane & 15;
    const int bsel = lane >> 4;

    for (int it = 0; it < 4; ++it) {
        const int vrow = it * 8 + w;
        const int gi   = bv0 + vrow;
        const int base = (gi / NV) * NV;

        int a = 0;
        if (lane < 16) a = adj[gi * KN + lane];
        const unsigned bal = __ballot_sync(0xffffffffu, a > 0);
        const int deg = __popc(bal & 0xffffu);
        const int j0  = (a > 0) ? (base + a - 1) : base;

        if (lane < 16) {
            const float validf = (a > 0) ? 1.0f : 0.0f;
            const float4 uc0 = *(const float4*)(g_uxc + gi * 12);
            const float4 uc1 = *(const float4*)(g_uxc + gi * 12 + 4);
            const float4 uc2 = *(const float4*)(g_uxc + gi * 12 + 8);
            const float4 vv0 = *(const float4*)(g_vxp + j0 * 12);
            const float4 vv1 = *(const float4*)(g_vxp + j0 * 12 + 4);
            const float4 vv2 = *(const float4*)(g_vxp + j0 * 12 + 8);
            float l[9];
            l[0] = (uc0.x + vv0.x) * validf; l[1] = (uc0.y + vv0.y) * validf;
            l[2] = (uc0.z + vv0.z) * validf; l[3] = (uc0.w + vv0.w) * validf;
            l[4] = (uc1.x + vv1.x) * validf; l[5] = (uc1.y + vv1.y) * validf;
            l[6] = (uc1.z + vv1.z) * validf; l[7] = (uc1.w + vv1.w) * validf;
            l[8] = (uc2.x + vv2.x) * validf;
            float mx = l[0];
            #pragma unroll
            for (int m = 1; m < 9; ++m) mx = fmaxf(mx, l[m]);
            float e[9], ssum = 0.f;
            #pragma unroll
            for (int m = 0; m < 9; ++m) { e[m] = __expf(l[m] - mx); ssum += e[m]; }
            float r;
            asm("rcp.approx.f32 %0, %1;" : "=f"(r) : "f"(ssum));
            r *= validf;

            uint32_t* qr = (uint32_t*)(smem + Q_OFF + (w * 16 + lane) * 48);
            qr[0] = f2h2(e[0]*r, e[1]*r);
            qr[1] = f2h2(e[2]*r, e[3]*r);
            qr[2] = f2h2(e[4]*r, e[5]*r);
            qr[3] = f2h2(e[6]*r, e[7]*r);
            qr[4] = f2h2(e[8]*r, 0.f);
            qr[5] = 0u; qr[6] = 0u; qr[7] = 0u;
        }
        __syncwarp();

        // gather 16 neighbor fp16 rows into swizzled xs tile
        #pragma unroll
        for (int p = 0; p < 4; ++p) {
            const int idx = lane + p * 32;
            const int row = idx >> 3;
            const int c16 = idx & 7;
            const int jr  = __shfl_sync(0xffffffffu, j0, row);
            const uint4 val = *(const uint4*)(g_xh + (size_t)jr * CC + c16 * 8);
            const uint32_t off = row * 128 + (((c16 ^ row) & 7) << 4);
            *(uint4*)(smem + XS_OFF + w * (16 * 128) + off) = val;
        }
        __syncwarp();

        uint32_t a0, a1, a2, a3;
        ldsm4t(a0, a1, a2, a3, aaddr1);

        float acc[8][4];
        #pragma unroll
        for (int nb = 0; nb < 8; ++nb)
            #pragma unroll
            for (int p = 0; p < 4; ++p) acc[nb][p] = 0.f;

        #pragma unroll
        for (int q = 0; q < 4; ++q) {
            const int chunk = 2 * q + bsel;
            const uint32_t baddr =
                xbase + brow * 128 + (((chunk ^ brow) & 7) << 4);
            uint32_t b0, b1, b2, b3;
            ldsm4t(b0, b1, b2, b3, baddr);
            mma16816(acc[2*q],     a0, a1, a2, a3, b0, b1);
            mma16816(acc[2*q + 1], a0, a1, a2, a3, b2, b3);
        }

        // epilogue -> smem s tile (rotated chunks, conflict-free)
        const float scl = (deg > 0) ? (1.0f / (float)deg) : 0.0f;
        uint32_t* srow = (uint32_t*)(smem + S_OFF + vrow * S_ROWB);
        const int m1 = lane >> 2;
        const int cw = lane & 3;
        #pragma unroll
        for (int nb = 0; nb < 8; ++nb) {
            const int c = m1 * 8 + nb;
            srow[swzc(c) * 4 + cw] = f2h2(acc[nb][0] * scl, acc[nb][1] * scl);
            if (m1 == 0) {
                const int c8 = 64 + nb;
                srow[swzc(c8) * 4 + cw] = f2h2(acc[nb][2] * scl, acc[nb][3] * scl);
            }
        }
        __syncwarp();
    }

    // ======================= PHASE 2 =======================
    // warp: rows rg*16 (rg = w>>2), cols cg4*16 (cg4 = w&3)
    const int rg  = w >> 2;
    const int cg4 = w & 3;
    const int grp = lane >> 3;
    const int rr  = lane & 7;
    const int mrow = (grp & 1) * 8 + rr;
    const int mcol = (grp >> 1) * 16;

    float acc2[2][4];
    #pragma unroll
    for (int j = 0; j < 2; ++j)
        #pragma unroll
        for (int p = 0; p < 4; ++p) acc2[j][p] = 0.f;

    const uint32_t arowaddr = sbase + (rg * 16 + mrow) * S_ROWB;

    for (int ch = 0; ch < 9; ++ch) {
        cpa_wait0();
        __syncthreads();   // chunk ch resident; s tile complete (ch 0); prev buf free

        if (ch < 8) stageB(ch + 1, (ch + 1) & 1);

        const uint32_t bb = bbase[ch & 1];
        #pragma unroll
        for (int k16 = 0; k16 < 4; ++k16) {
            const int c = ch * 8 + k16 * 2 + (mcol >> 4);
            uint32_t a0, a1, a2, a3;
            ldsm4(a0, a1, a2, a3, arowaddr + swzc(c) * 16);
            uint32_t boff = (uint32_t)((cg4 * 16 + mrow) * 128 + mcol + k16 * 32);
            boff ^= (boff >> 3) & 0x70;
            uint32_t b0, b1, b2, b3;
            ldsm4(b0, b1, b2, b3, bb + boff);
            mma16816(acc2[0], a0, a1, a2, a3, b0, b2);
            mma16816(acc2[1], a0, a1, a2, a3, b1, b3);
        }
    }

    // ---- epilogue: C frags + bias -> gmem ----
    const int crow = bv0 + rg * 16 + (lane >> 2);
    const int ccol = cg4 * 16 + (lane & 3) * 2;
    #pragma unroll
    for (int j = 0; j < 2; ++j) {
        const int nb = ccol + j * 8;
        const float2 bv = *(const float2*)(bias + nb);
        *(float2*)(out + (size_t)crow * OO + nb) =
            make_float2(acc2[j][0] + bv.x, acc2[j][1] + bv.y);
        *(float2*)(out + (size_t)(crow + 8) * OO + nb) =
            make_float2(acc2[j][2] + bv.x, acc2[j][3] + bv.y);
    }
}

// ---------------------------------------------------------------------------
// Host launcher (graph-capturable: kernel launches only)
// ---------------------------------------------------------------------------
extern "C" void kernel_launch(void* const* d_in, const int* in_sizes, int n_in,
                              void* d_out, int out_size) {
    const float* x   = (const float*)d_in[0];  // [B,N,C]
    const int*   adj = (const int*)  d_in[1];  // [B,N,K]
    const float* W   = (const float*)d_in[2];  // [M,O,C]
    const float* b   = (const float*)d_in[3];  // [O]
    const float* u   = (const float*)d_in[4];  // [M,C]
    const float* v   = (const float*)d_in[5];  // [M,C]
    const float* c   = (const float*)d_in[6];  // [M]
    float* out = (float*)d_out;

    feast_prep<<<UVX_BLOCKS + (MM * OO * CC + 255) / 256, 256>>>(x, u, v, c, W);

    cudaFuncSetAttribute(feast_fused, cudaFuncAttributeMaxDynamicSharedMemorySize,
                         FSMEM);
    feast_fused<<<NVT / 32, 256, FSMEM>>>(adj, b, out);
}

// round 15
// speedup vs baseline: 1.3554x; 1.0689x over previous
#include <cuda_runtime.h>
#include <cuda_fp16.h>
#include <cstdint>
#include <cstddef>
#include <cstring>

// Problem constants (fixed by the dataset)
#define NV    20000            // vertices per batch
#define NVT   80000            // B * N
#define KN    16               // neighbors
#define MM    9                // kernels
#define CC    64               // in channels
#define OO    64               // out channels
#define GK    576              // GEMM K (M * C)

// Device-global scratch (sanctioned workaround for no-alloc rule)
__device__ float g_uxc[NVT * 12];                        // ux + c (pad 12)
__device__ float g_vxp[NVT * 12];                        // vx     (pad 12)
__device__ __align__(16) __half g_xh[(size_t)NVT * CC];  // x in fp16
__device__ __align__(16) __half g_wb[OO * GK];           // B[o][k] = W[m][o][c]

// ---- packed fp32x2 helpers ----
__device__ __forceinline__ void fma2(unsigned long long& acc,
                                     unsigned long long a,
                                     unsigned long long b) {
    asm("fma.rn.f32x2 %0, %1, %2, %0;" : "+l"(acc) : "l"(a), "l"(b));
}
__device__ __forceinline__ unsigned long long pack2(float x, float y) {
    unsigned long long r;
    asm("mov.b64 %0, {%1, %2};" : "=l"(r) : "f"(x), "f"(y));
    return r;
}
__device__ __forceinline__ float2 unpack2(unsigned long long a) {
    float2 r;
    asm("mov.b64 {%0, %1}, %2;" : "=f"(r.x), "=f"(r.y) : "l"(a));
    return r;
}
// ---- half2 bit-cast helpers ----
__device__ __forceinline__ uint32_t h2u(__half2 h) {
    uint32_t r;
    memcpy(&r, &h, 4);
    return r;
}
__device__ __forceinline__ uint32_t f2h2(float x, float y) {
    return h2u(__floats2half2_rn(x, y));
}
// ---- cp.async helpers ----
__device__ __forceinline__ void cpa16(uint32_t dst_smem, const void* src) {
    asm volatile("cp.async.cg.shared.global [%0], [%1], 16;"
                 :: "r"(dst_smem), "l"(src));
}
__device__ __forceinline__ void cpa_commit() {
    asm volatile("cp.async.commit_group;");
}
__device__ __forceinline__ void cpa_wait0() {
    asm volatile("cp.async.wait_group 0;");
}
__device__ __forceinline__ uint32_t smem_u32(const void* p) {
    uint32_t a;
    asm("{ .reg .u64 t; cvta.to.shared.u64 t, %1; cvt.u32.u64 %0, t; }"
        : "=r"(a) : "l"(p));
    return a;
}
// ---- tensor-core primitives (baseline PTX, sm_75+/80+) ----
__device__ __forceinline__ void ldsm4(uint32_t& r0, uint32_t& r1, uint32_t& r2,
                                      uint32_t& r3, uint32_t addr) {
    asm volatile("ldmatrix.sync.aligned.m8n8.x4.shared.b16 {%0,%1,%2,%3}, [%4];"
                 : "=r"(r0), "=r"(r1), "=r"(r2), "=r"(r3) : "r"(addr));
}
__device__ __forceinline__ void ldsm4t(uint32_t& r0, uint32_t& r1, uint32_t& r2,
                                       uint32_t& r3, uint32_t addr) {
    asm volatile("ldmatrix.sync.aligned.m8n8.x4.trans.shared.b16 {%0,%1,%2,%3}, [%4];"
                 : "=r"(r0), "=r"(r1), "=r"(r2), "=r"(r3) : "r"(addr));
}
__device__ __forceinline__ void mma16816(float* c, uint32_t a0, uint32_t a1,
                                         uint32_t a2, uint32_t a3,
                                         uint32_t b0, uint32_t b1) {
    asm volatile(
        "mma.sync.aligned.m16n8k16.row.col.f32.f16.f16.f32 "
        "{%0,%1,%2,%3}, {%4,%5,%6,%7}, {%8,%9}, {%0,%1,%2,%3};"
        : "+f"(c[0]), "+f"(c[1]), "+f"(c[2]), "+f"(c[3])
        : "r"(a0), "r"(a1), "r"(a2), "r"(a3), "r"(b0), "r"(b1));
}
// per-group chunk rotation (16B granularity): spreads same-row chunks across banks
__device__ __forceinline__ int swzc(int c) {
    return (c & ~7) | ((c + (c >> 3)) & 7);
}

// ---------------------------------------------------------------------------
// Kernel 1 (merged prep): blocks [0, 625) -> lane-PAIR-per-vertex projections
//                         + x -> fp16 copy; blocks [625, +144) -> W -> fp16 B
// ---------------------------------------------------------------------------
#define UVX_BLOCKS 625          // 80000 / 128 vertices per block

__global__ void __launch_bounds__(256)
feast_prep(const float* __restrict__ x, const float* __restrict__ u,
           const float* __restrict__ v, const float* __restrict__ c,
           const float* __restrict__ W) {
    if (blockIdx.x < UVX_BLOCKS) {
        __shared__ float uv_sm[18 * 64];
        __shared__ float c_sm[MM];
        for (int i = threadIdx.x; i < 576; i += 256) {
            uv_sm[i]       = u[i];
            uv_sm[576 + i] = v[i];
        }
        if (threadIdx.x < MM) c_sm[threadIdx.x] = c[threadIdx.x];
        __syncthreads();

        const int pairid = threadIdx.x >> 1;       // vertex within block
        const int hf     = threadIdx.x & 1;        // channel half (0: 0-31)
        const int gi     = blockIdx.x * 128 + pairid;

        unsigned long long xr[16];
        {
            const float4* xp = (const float4*)(x + (size_t)gi * CC + hf * 32);
            #pragma unroll
            for (int i = 0; i < 8; ++i) {
                const float4 t = xp[i];
                xr[2*i]   = pack2(t.x, t.y);
                xr[2*i+1] = pack2(t.z, t.w);
            }
        }
        {
            uint4* dst = (uint4*)(g_xh + (size_t)gi * CC + hf * 32);
            #pragma unroll
            for (int i = 0; i < 4; ++i) {
                const float2 f0 = unpack2(xr[4*i]);
                const float2 f1 = unpack2(xr[4*i+1]);
                const float2 f2 = unpack2(xr[4*i+2]);
                const float2 f3 = unpack2(xr[4*i+3]);
                uint4 o;
                o.x = f2h2(f0.x, f0.y);
                o.y = f2h2(f1.x, f1.y);
                o.z = f2h2(f2.x, f2.y);
                o.w = f2h2(f3.x, f3.y);
                dst[i] = o;
            }
        }
        #pragma unroll
        for (int m = 0; m < MM; ++m) {
            const unsigned long long* um =
                (const unsigned long long*)(uv_sm + m * 64 + hf * 32);
            const unsigned long long* vm =
                (const unsigned long long*)(uv_sm + 576 + m * 64 + hf * 32);
            unsigned long long pu = 0ull, pv = 0ull;
            #pragma unroll
            for (int i = 0; i < 16; ++i) {
                fma2(pu, xr[i], um[i]);
                fma2(pv, xr[i], vm[i]);
            }
            const float2 fu = unpack2(pu);
            const float2 fv = unpack2(pv);
            float su = fu.x + fu.y;
            float sv = fv.x + fv.y;
            su += __shfl_xor_sync(0xffffffffu, su, 1);
            sv += __shfl_xor_sync(0xffffffffu, sv, 1);
            if (hf == 0) {
                g_uxc[gi * 12 + m] = su + c_sm[m];
                g_vxp[gi * 12 + m] = sv;
            }
        }
    } else {
        const int tid = (blockIdx.x - UVX_BLOCKS) * 256 + threadIdx.x;
        if (tid >= MM * OO * CC) return;
        const int cc = tid & 63;
        const int o  = (tid >> 6) & 63;
        const int m  = tid >> 12;
        g_wb[o * GK + m * 64 + cc] = __float2half_rn(W[tid]);
    }
}

// ---------------------------------------------------------------------------
// Kernel 2 (FUSED): gather + softmax + HMMA s (to smem) + HMMA GEMM + bias
// CTA = 32 vertices, 3 CTAs/SM. Wb buf0 dedicated; buf1 ALIASES the XS gather
// region (dead in phase 2) -> smem drops to 66.5 KB.
// ---------------------------------------------------------------------------
// smem layout (bytes from base):
#define S_OFF   0                        // 32 rows x 1168 B (584 halfs)
#define S_ROWB  1168
#define XS_OFF  37376                    // 8 warps x 16 x 128 B (phase 1 only)
#define Q_OFF   53760                    // 8 warps x 16 x 48 B  (phase 1 only)
#define B0_OFF  59904                    // Wb chunk buf 0 (8 KB, dedicated)
#define FSMEM   68096
// Wb chunk buf 1 aliases XS_OFF (staged only after phase 1 completes)

__global__ void __launch_bounds__(256, 3)
feast_fused(const int* __restrict__ adj, const float* __restrict__ bias,
            float* __restrict__ out) {
    extern __shared__ char smem[];
    const uint32_t sb    = smem_u32(smem);
    const uint32_t sbase = sb + S_OFF;
    const uint32_t bbase[2] = { sb + B0_OFF, sb + XS_OFF };  // buf1 aliases XS

    const int tid  = threadIdx.x;
    const int w    = tid >> 5;
    const int lane = tid & 31;
    const int bv0  = blockIdx.x * 32;

    // stage Wb chunk ch (64 o-rows x 64 halfs, SW128 swizzled) into buffer b
    auto stageB = [&](int ch, int b) {
        const __half* bsrc = g_wb + ch * 64;
        #pragma unroll
        for (int i = 0; i < 2; ++i) {
            const int uu = tid + i * 256;
            const int row = uu >> 3, cu = uu & 7;
            uint32_t off = (uint32_t)(row * 128 + cu * 16);
            off ^= (off >> 3) & 0x70;
            cpa16(bbase[b] + off, bsrc + (size_t)row * GK + cu * 8);
        }
        cpa_commit();
    };
    stageB(0, 0);   // into dedicated buf0; flows in under phase 1

    // ======================= PHASE 1 =======================
    const uint32_t qbase = sb + Q_OFF + w * (16 * 48);
    const uint32_t xbase = sb + XS_OFF + w * (16 * 128);
    const int arow = (lane & 7) + ((lane & 16) >> 1);
    const uint32_t aaddr1 = qbase + arow * 48 + ((lane & 8) << 1);
    const int brow = lane & 15;
    const int bsel = lane >> 4;

    for (int it = 0; it < 4; ++it) {
        const int vrow = it * 8 + w;
        const int gi   = bv0 + vrow;
        const int base = (gi / NV) * NV;

        int a = 0;
        if (lane < 16) a = adj[gi * KN + lane];
        const unsigned bal = __ballot_sync(0xffffffffu, a > 0);
        const int deg = __popc(bal & 0xffffu);
        const int j0  = (a > 0) ? (base + a - 1) : base;

        if (lane < 16) {
            const float validf = (a > 0) ? 1.0f : 0.0f;
            const float4 uc0 = *(const float4*)(g_uxc + gi * 12);
            const float4 uc1 = *(const float4*)(g_uxc + gi * 12 + 4);
            const float4 uc2 = *(const float4*)(g_uxc + gi * 12 + 8);
            const float4 vv0 = *(const float4*)(g_vxp + j0 * 12);
            const float4 vv1 = *(const float4*)(g_vxp + j0 * 12 + 4);
            const float4 vv2 = *(const float4*)(g_vxp + j0 * 12 + 8);
            float l[9];
            l[0] = (uc0.x + vv0.x) * validf; l[1] = (uc0.y + vv0.y) * validf;
            l[2] = (uc0.z + vv0.z) * validf; l[3] = (uc0.w + vv0.w) * validf;
            l[4] = (uc1.x + vv1.x) * validf; l[5] = (uc1.y + vv1.y) * validf;
            l[6] = (uc1.z + vv1.z) * validf; l[7] = (uc1.w + vv1.w) * validf;
            l[8] = (uc2.x + vv2.x) * validf;
            float mx = l[0];
            #pragma unroll
            for (int m = 1; m < 9; ++m) mx = fmaxf(mx, l[m]);
            float e[9], ssum = 0.f;
            #pragma unroll
            for (int m = 0; m < 9; ++m) { e[m] = __expf(l[m] - mx); ssum += e[m]; }
            float r;
            asm("rcp.approx.f32 %0, %1;" : "=f"(r) : "f"(ssum));
            r *= validf;

            uint32_t* qr = (uint32_t*)(smem + Q_OFF + (w * 16 + lane) * 48);
            qr[0] = f2h2(e[0]*r, e[1]*r);
            qr[1] = f2h2(e[2]*r, e[3]*r);
            qr[2] = f2h2(e[4]*r, e[5]*r);
            qr[3] = f2h2(e[6]*r, e[7]*r);
            qr[4] = f2h2(e[8]*r, 0.f);
            qr[5] = 0u; qr[6] = 0u; qr[7] = 0u;
        }
        __syncwarp();

        // gather 16 neighbor fp16 rows into swizzled xs tile
        #pragma unroll
        for (int p = 0; p < 4; ++p) {
            const int idx = lane + p * 32;
            const int row = idx >> 3;
            const int c16 = idx & 7;
            const int jr  = __shfl_sync(0xffffffffu, j0, row);
            const uint4 val = *(const uint4*)(g_xh + (size_t)jr * CC + c16 * 8);
            const uint32_t off = row * 128 + (((c16 ^ row) & 7) << 4);
            *(uint4*)(smem + XS_OFF + w * (16 * 128) + off) = val;
        }
        __syncwarp();

        uint32_t a0, a1, a2, a3;
        ldsm4t(a0, a1, a2, a3, aaddr1);

        float acc[8][4];
        #pragma unroll
        for (int nb = 0; nb < 8; ++nb)
            #pragma unroll
            for (int p = 0; p < 4; ++p) acc[nb][p] = 0.f;

        #pragma unroll
        for (int q = 0; q < 4; ++q) {
            const int chunk = 2 * q + bsel;
            const uint32_t baddr =
                xbase + brow * 128 + (((chunk ^ brow) & 7) << 4);
            uint32_t b0, b1, b2, b3;
            ldsm4t(b0, b1, b2, b3, baddr);
            mma16816(acc[2*q],     a0, a1, a2, a3, b0, b1);
            mma16816(acc[2*q + 1], a0, a1, a2, a3, b2, b3);
        }

        // epilogue -> smem s tile (rotated chunks, conflict-free)
        const float scl = (deg > 0) ? (1.0f / (float)deg) : 0.0f;
        uint32_t* srow = (uint32_t*)(smem + S_OFF + vrow * S_ROWB);
        const int m1 = lane >> 2;
        const int cw = lane & 3;
        #pragma unroll
        for (int nb = 0; nb < 8; ++nb) {
            const int c = m1 * 8 + nb;
            srow[swzc(c) * 4 + cw] = f2h2(acc[nb][0] * scl, acc[nb][1] * scl);
            if (m1 == 0) {
                const int c8 = 64 + nb;
                srow[swzc(c8) * 4 + cw] = f2h2(acc[nb][2] * scl, acc[nb][3] * scl);
            }
        }
        __syncwarp();
    }

    // ======================= PHASE 2 =======================
    // warp: rows rg*16 (rg = w>>2), cols cg4*16 (cg4 = w&3)
    const int rg  = w >> 2;
    const int cg4 = w & 3;
    const int grp = lane >> 3;
    const int rr  = lane & 7;
    const int mrow = (grp & 1) * 8 + rr;
    const int mcol = (grp >> 1) * 16;

    float acc2[2][4];
    #pragma unroll
    for (int j = 0; j < 2; ++j)
        #pragma unroll
        for (int p = 0; p < 4; ++p) acc2[j][p] = 0.f;

    const uint32_t arowaddr = sbase + (rg * 16 + mrow) * S_ROWB;

    for (int ch = 0; ch < 9; ++ch) {
        cpa_wait0();
        __syncthreads();   // chunk ch resident; phase 1 done (ch 0); prev buf free

        if (ch < 8) stageB(ch + 1, (ch + 1) & 1);   // buf1 = XS region (now dead)

        const uint32_t bb = bbase[ch & 1];
        #pragma unroll
        for (int k16 = 0; k16 < 4; ++k16) {
            const int c = ch * 8 + k16 * 2 + (mcol >> 4);
            uint32_t a0, a1, a2, a3;
            ldsm4(a0, a1, a2, a3, arowaddr + swzc(c) * 16);
            uint32_t boff = (uint32_t)((cg4 * 16 + mrow) * 128 + mcol + k16 * 32);
            boff ^= (boff >> 3) & 0x70;
            uint32_t b0, b1, b2, b3;
            ldsm4(b0, b1, b2, b3, bb + boff);
            mma16816(acc2[0], a0, a1, a2, a3, b0, b2);
            mma16816(acc2[1], a0, a1, a2, a3, b1, b3);
        }
    }

    // ---- epilogue: C frags + bias -> gmem ----
    const int crow = bv0 + rg * 16 + (lane >> 2);
    const int ccol = cg4 * 16 + (lane & 3) * 2;
    #pragma unroll
    for (int j = 0; j < 2; ++j) {
        const int nb = ccol + j * 8;
        const float2 bv = *(const float2*)(bias + nb);
        *(float2*)(out + (size_t)crow * OO + nb) =
            make_float2(acc2[j][0] + bv.x, acc2[j][1] + bv.y);
        *(float2*)(out + (size_t)(crow + 8) * OO + nb) =
            make_float2(acc2[j][2] + bv.x, acc2[j][3] + bv.y);
    }
}

// ---------------------------------------------------------------------------
// Host launcher (graph-capturable: kernel launches only)
// ---------------------------------------------------------------------------
extern "C" void kernel_launch(void* const* d_in, const int* in_sizes, int n_in,
                              void* d_out, int out_size) {
    const float* x   = (const float*)d_in[0];  // [B,N,C]
    const int*   adj = (const int*)  d_in[1];  // [B,N,K]
    const float* W   = (const float*)d_in[2];  // [M,O,C]
    const float* b   = (const float*)d_in[3];  // [O]
    const float* u   = (const float*)d_in[4];  // [M,C]
    const float* v   = (const float*)d_in[5];  // [M,C]
    const float* c   = (const float*)d_in[6];  // [M]
    float* out = (float*)d_out;

    feast_prep<<<UVX_BLOCKS + (MM * OO * CC + 255) / 256, 256>>>(x, u, v, c, W);

    cudaFuncSetAttribute(feast_fused, cudaFuncAttributeMaxDynamicSharedMemorySize,
                         FSMEM);
    feast_fused<<<NVT / 32, 256, FSMEM>>>(adj, b, out);
}